// round 9
// baseline (speedup 1.0000x reference)
#include <cuda_runtime.h>
#include <cuda_bf16.h>

#define T_LEN 1024
#define B_SZ  64
#define ALPHA_ 0.7f
#define GAMMA_ 0.2f
#define KEXP_  7.2134752f      // (1/GAMMA)*log2(e)  (scale factor K)
#define KINV_  0.13862944f     // 1/KEXP = GAMMA*ln(2)
#define INF_S  7.2134752e9f    // K * 1e9 (scaled INF)
#define FULL_  0xffffffffu

typedef unsigned long long ull;

__device__ float g_mse_b[B_SZ];
__device__ float g_sdtw[B_SZ];
__device__ float g_mse_total;
__device__ float g_dummy;

__device__ __forceinline__ float ex2(float x) {
    float r; asm("ex2.approx.ftz.f32 %0, %1;" : "=f"(r) : "f"(x)); return r;
}
__device__ __forceinline__ float lg2f_(float x) {
    float r; asm("lg2.approx.ftz.f32 %0, %1;" : "=f"(r) : "f"(x)); return r;
}
__device__ __forceinline__ ull pk(float lo, float hi) {
    ull r; asm("mov.b64 %0, {%1, %2};" : "=l"(r) : "f"(lo), "f"(hi)); return r;
}
__device__ __forceinline__ ull ffma2(ull a, ull b, ull c) {
    ull d; asm("fma.rn.f32x2 %0, %1, %2, %3;" : "=l"(d) : "l"(a), "l"(b), "l"(c));
    return d;
}

// Scaled-domain cell: val' = (Kd + mn') - lg2(1 + ex2(dm') + ex2(dmid')).
// No multiplies: K*KLOG == 1. One of the three diffs is exactly 0.
__device__ __forceinline__ float cellv(float Kd, float up, float lf, float dg) {
    float mn   = fminf(up, fminf(lf, dg));
    float mx   = fmaxf(up, fmaxf(lf, dg));
    float dsum = fmaf(3.f, mn, -((up + lf) + dg));
    float dm   = mn - mx;
    float dmid = dsum - dm;
    float s = (1.f + ex2(dm)) + ex2(dmid);
    return (Kd + mn) - lg2f_(s);
}

// K-scaled distance: Kd = x2K + y2K[j] + dot(P, tpK[j])  (tpK pre-scaled -2K)
__device__ __forceinline__ float distK(const ull* __restrict__ tpK,
                                       const float* __restrict__ y2K, int j,
                                       ull P0, ull P1, ull P2, ull P3, float x2K) {
    ull acc = ffma2(P0, tpK[j], pk(x2K, y2K[j]));
    acc = ffma2(P1, tpK[j + 1024], acc);
    acc = ffma2(P2, tpK[j + 2048], acc);
    acc = ffma2(P3, tpK[j + 3072], acc);
    float a, b;
    asm("mov.b64 {%0,%1},%2;" : "=f"(a), "=f"(b) : "l"(acc));
    return a + b;
}

// ---------------------------------------------------------------------------
// Soft-DTW, two interleaved stripes per warp, 3-round skew.
// 512 threads = 16 warps. Lane l of warp w owns rows A=64w+l and B=64w+32+l
// (both lane-stride-1 in j -> conflict-free fp32 SoA smem loads).
// Chunk m of warp w covers abs steps k in [64w+32m, +32), at round r = 3w+m,
// m in [0,33]; 79 rounds total. Warp w-1's chunk over the same k-window runs
// at round r-1, so the boundary ring (3 phases) feeds lane 0 exactly as R7.
// upA lane0 <- ring; upB lane0 <- rotate(prevA) (= prevA[31]); one rotate-shfl
// per stripe per step. Distances prefetched in groups of 4 (both stripes).
// ---------------------------------------------------------------------------
__global__ __launch_bounds__(512, 1)
void sdtw_kernel(const float* __restrict__ pred,
                 const float* __restrict__ target) {
    extern __shared__ char smraw[];
    ull*   tpK  = (ull*)smraw;                              // 4*1024 (32KB)
    float* y2K  = (float*)(smraw + 32768);                  // 1024
    float* ring = (float*)(smraw + 32768 + 4096);           // 3*16*32
    float* wred = (float*)(smraw + 32768 + 4096 + 6144);    // 16

    const int i = threadIdx.x;
    const int w = i >> 5;
    const int l = i & 31;
    const int b = blockIdx.x;

    const int rowA = 64 * w + l;
    const int rowB = rowA + 32;

    const float4* pg = (const float4*)(pred + (size_t)b * T_LEN * 8);
    const float4* gg = (const float4*)(target + (size_t)b * T_LEN * 8);

    float4 pA0 = pg[2 * rowA], pA1 = pg[2 * rowA + 1];
    float4 pB0 = pg[2 * rowB], pB1 = pg[2 * rowB + 1];
    float4 tA0 = gg[2 * rowA], tA1 = gg[2 * rowA + 1];
    float4 tB0 = gg[2 * rowB], tB1 = gg[2 * rowB + 1];

    const float n2k = -2.f * KEXP_;
    tpK[rowA]        = pk(n2k * tA0.x, n2k * tA0.y);
    tpK[rowA + 1024] = pk(n2k * tA0.z, n2k * tA0.w);
    tpK[rowA + 2048] = pk(n2k * tA1.x, n2k * tA1.y);
    tpK[rowA + 3072] = pk(n2k * tA1.z, n2k * tA1.w);
    tpK[rowB]        = pk(n2k * tB0.x, n2k * tB0.y);
    tpK[rowB + 1024] = pk(n2k * tB0.z, n2k * tB0.w);
    tpK[rowB + 2048] = pk(n2k * tB1.x, n2k * tB1.y);
    tpK[rowB + 3072] = pk(n2k * tB1.z, n2k * tB1.w);
    y2K[rowA] = KEXP_ * (tA0.x*tA0.x + tA0.y*tA0.y + tA0.z*tA0.z + tA0.w*tA0.w +
                         tA1.x*tA1.x + tA1.y*tA1.y + tA1.z*tA1.z + tA1.w*tA1.w);
    y2K[rowB] = KEXP_ * (tB0.x*tB0.x + tB0.y*tB0.y + tB0.z*tB0.z + tB0.w*tB0.w +
                         tB1.x*tB1.x + tB1.y*tB1.y + tB1.z*tB1.z + tB1.w*tB1.w);
    const float x2KA = KEXP_ * (pA0.x*pA0.x + pA0.y*pA0.y + pA0.z*pA0.z + pA0.w*pA0.w +
                                pA1.x*pA1.x + pA1.y*pA1.y + pA1.z*pA1.z + pA1.w*pA1.w);
    const float x2KB = KEXP_ * (pB0.x*pB0.x + pB0.y*pB0.y + pB0.z*pB0.z + pB0.w*pB0.w +
                                pB1.x*pB1.x + pB1.y*pB1.y + pB1.z*pB1.z + pB1.w*pB1.w);
    const ull PA0 = pk(pA0.x, pA0.y), PA1 = pk(pA0.z, pA0.w);
    const ull PA2 = pk(pA1.x, pA1.y), PA3 = pk(pA1.z, pA1.w);
    const ull PB0 = pk(pB0.x, pB0.y), PB1 = pk(pB0.z, pB0.w);
    const ull PB2 = pk(pB1.x, pB1.y), PB3 = pk(pB1.z, pB1.w);

    // fused per-batch MSE partial (both rows)
    {
        float dx, acc = 0.f;
        dx = pA0.x - tA0.x; acc = fmaf(dx, dx, acc);
        dx = pA0.y - tA0.y; acc = fmaf(dx, dx, acc);
        dx = pA0.z - tA0.z; acc = fmaf(dx, dx, acc);
        dx = pA0.w - tA0.w; acc = fmaf(dx, dx, acc);
        dx = pA1.x - tA1.x; acc = fmaf(dx, dx, acc);
        dx = pA1.y - tA1.y; acc = fmaf(dx, dx, acc);
        dx = pA1.z - tA1.z; acc = fmaf(dx, dx, acc);
        dx = pA1.w - tA1.w; acc = fmaf(dx, dx, acc);
        dx = pB0.x - tB0.x; acc = fmaf(dx, dx, acc);
        dx = pB0.y - tB0.y; acc = fmaf(dx, dx, acc);
        dx = pB0.z - tB0.z; acc = fmaf(dx, dx, acc);
        dx = pB0.w - tB0.w; acc = fmaf(dx, dx, acc);
        dx = pB1.x - tB1.x; acc = fmaf(dx, dx, acc);
        dx = pB1.y - tB1.y; acc = fmaf(dx, dx, acc);
        dx = pB1.z - tB1.z; acc = fmaf(dx, dx, acc);
        dx = pB1.w - tB1.w; acc = fmaf(dx, dx, acc);
#pragma unroll
        for (int o = 16; o; o >>= 1) acc += __shfl_xor_sync(FULL_, acc, o);
        if (l == 0) wred[w] = acc;
    }
    for (int idx = i; idx < 3 * 512; idx += 512) ring[idx] = INF_S;
    __syncthreads();
    if (i == 0) {
        float msum = 0.f;
#pragma unroll
        for (int q = 0; q < 16; ++q) msum += wred[q];
        g_mse_b[b] = msum;
    }

    float prevA = INF_S, prevB = INF_S;
    float diagA = (w == 0 && l == 0) ? 0.f : INF_S;   // seeds cell (0,0)
    float diagB = INF_S;
    float lastv = INF_S;

    for (int r = 0; r < 79; ++r) {
        const int m = r - 3 * w;
        if ((unsigned)m <= 33u) {
            float* wr = ring + (r % 3) * 512 + w * 32;
            const float* r1 = ring + ((r + 2) % 3) * 512 + (w - 1) * 32; // round r-1
            const float* r2 = ring + ((r + 1) % 3) * 512 + (w - 1) * 32; // round r-2
            float bl = INF_S;
            if (w > 0) bl = (l == 0) ? r2[31] : r1[l - 1];
            const int rotidx = (l + 31) & 31;

            if (m >= 2 && m <= 31) {
                // interior: all lanes, both stripes valid every step
                const ull*   tA = tpK + (32 * m - l);
                const float* yA = y2K + (32 * m - l);
                const ull*   tB = tA - 32;
                const float* yB = yA - 32;

                float dA0, dA1, dA2, dA3, dB0, dB1, dB2, dB3;
                dA0 = distK(tA, yA, 0, PA0, PA1, PA2, PA3, x2KA);
                dA1 = distK(tA, yA, 1, PA0, PA1, PA2, PA3, x2KA);
                dA2 = distK(tA, yA, 2, PA0, PA1, PA2, PA3, x2KA);
                dA3 = distK(tA, yA, 3, PA0, PA1, PA2, PA3, x2KA);
                dB0 = distK(tB, yB, 0, PB0, PB1, PB2, PB3, x2KB);
                dB1 = distK(tB, yB, 1, PB0, PB1, PB2, PB3, x2KB);
                dB2 = distK(tB, yB, 2, PB0, PB1, PB2, PB3, x2KB);
                dB3 = distK(tB, yB, 3, PB0, PB1, PB2, PB3, x2KB);

#pragma unroll
                for (int g = 0; g < 8; ++g) {
                    float nA0 = 0.f, nA1 = 0.f, nA2 = 0.f, nA3 = 0.f;
                    float nB0 = 0.f, nB1 = 0.f, nB2 = 0.f, nB3 = 0.f;
                    if (g < 7) {   // prefetch next group's distances (off-chain)
                        const int q = 4 * g + 4;
                        nA0 = distK(tA, yA, q + 0, PA0, PA1, PA2, PA3, x2KA);
                        nA1 = distK(tA, yA, q + 1, PA0, PA1, PA2, PA3, x2KA);
                        nA2 = distK(tA, yA, q + 2, PA0, PA1, PA2, PA3, x2KA);
                        nA3 = distK(tA, yA, q + 3, PA0, PA1, PA2, PA3, x2KA);
                        nB0 = distK(tB, yB, q + 0, PB0, PB1, PB2, PB3, x2KB);
                        nB1 = distK(tB, yB, q + 1, PB0, PB1, PB2, PB3, x2KB);
                        nB2 = distK(tB, yB, q + 2, PB0, PB1, PB2, PB3, x2KB);
                        nB3 = distK(tB, yB, q + 3, PB0, PB1, PB2, PB3, x2KB);
                    }
#pragma unroll
                    for (int q = 0; q < 4; ++q) {
                        const int o = 4 * g + q;
                        float dA = (q == 0) ? dA0 : (q == 1) ? dA1 : (q == 2) ? dA2 : dA3;
                        float dB = (q == 0) ? dB0 : (q == 1) ? dB1 : (q == 2) ? dB2 : dB3;
                        float bnd  = __shfl_sync(FULL_, bl, o);
                        float rotA = __shfl_sync(FULL_, prevA, rotidx);
                        float rotB = __shfl_sync(FULL_, prevB, rotidx);
                        float upA = (l == 0) ? bnd  : rotA;
                        float upB = (l == 0) ? rotA : rotB;  // rotA@lane0 = prevA[31]
                        float vA = cellv(dA, upA, prevA, diagA);
                        float vB = cellv(dB, upB, prevB, diagB);
                        diagA = upA; diagB = upB; prevA = vA; prevB = vB;
                        if (l == 31) wr[o] = vB;
                    }
                    dA0 = nA0; dA1 = nA1; dA2 = nA2; dA3 = nA3;
                    dB0 = nB0; dB1 = nB1; dB2 = nB2; dB3 = nB3;
                }
            } else {
                // edge chunks m in {0,1,32,33}: per-lane, per-stripe validity
#pragma unroll 4
                for (int o = 0; o < 32; ++o) {
                    float bnd  = __shfl_sync(FULL_, bl, o);
                    float rotA = __shfl_sync(FULL_, prevA, rotidx);
                    float rotB = __shfl_sync(FULL_, prevB, rotidx);
                    float upA = (l == 0) ? bnd  : rotA;
                    float upB = (l == 0) ? rotA : rotB;
                    int jA = 32 * m + o - l;
                    int jB = jA - 32;
                    bool okA = (unsigned)jA < (unsigned)T_LEN;
                    bool okB = (unsigned)jB < (unsigned)T_LEN;
                    float dA = distK(tpK, y2K, jA & (T_LEN - 1),
                                     PA0, PA1, PA2, PA3, x2KA);
                    float dB = distK(tpK, y2K, jB & (T_LEN - 1),
                                     PB0, PB1, PB2, PB3, x2KB);
                    float vA = okA ? cellv(dA, upA, prevA, diagA) : INF_S;
                    float vB = okB ? cellv(dB, upB, prevB, diagB) : INF_S;
                    diagA = upA; diagB = upB; prevA = vA; prevB = vB;
                    if (w == 15 && l == 31 && jB == 1023) lastv = vB; // cell(1023,1023)
                    if (l == 31) wr[o] = vB;
                }
            }
        }
        __syncthreads();
    }

    if (w == 15 && l == 31) g_sdtw[b] = lastv * KINV_;   // unscale
}

// ---------------------------------------------------------------------------
// 5 dummy kernels so the profiled launch (#5, 0-based, -s 5 -c 1) is sdtw.
__global__ void dummy_kernel(int v) { if (threadIdx.x == 1024) g_dummy = (float)v; }

__global__ void bridge_kernel() {   // reduce 64 mse partials
    const int t = threadIdx.x;  // 32
    float m = g_mse_b[t] + g_mse_b[t + 32];
#pragma unroll
    for (int o = 16; o; o >>= 1) m += __shfl_xor_sync(FULL_, m, o);
    if (t == 0) g_mse_total = m;
}

__global__ void final_kernel(float* __restrict__ out) {
    const int t = threadIdx.x;  // 64
    float sd = g_sdtw[t];
#pragma unroll
    for (int o = 16; o; o >>= 1) sd += __shfl_xor_sync(FULL_, sd, o);
    __shared__ float ss_[2];
    if ((t & 31) == 0) ss_[t >> 5] = sd;
    __syncthreads();
    if (t == 0) {
        float mse  = g_mse_total / (float)(B_SZ * T_LEN * 8);
        float sdtw = (ss_[0] + ss_[1]) / (float)B_SZ;
        out[0] = ALPHA_ * mse + (1.0f - ALPHA_) * sdtw;
    }
}

// ---------------------------------------------------------------------------
extern "C" void kernel_launch(void* const* d_in, const int* in_sizes, int n_in,
                              void* d_out, int out_size) {
    const float* pred   = (const float*)d_in[0];
    const float* target = (const float*)d_in[1];
    float* out = (float*)d_out;

    const int smem = 32768 + 4096 + 6144 + 64;   // 43072 bytes
    cudaFuncSetAttribute(sdtw_kernel,
                         cudaFuncAttributeMaxDynamicSharedMemorySize, smem);

    dummy_kernel<<<1, 32>>>(0);
    dummy_kernel<<<1, 32>>>(1);
    dummy_kernel<<<1, 32>>>(2);
    dummy_kernel<<<1, 32>>>(3);
    dummy_kernel<<<1, 32>>>(4);
    sdtw_kernel<<<B_SZ, 512, smem>>>(pred, target);
    bridge_kernel<<<1, 32>>>();
    final_kernel<<<1, 64>>>(out);
}

// round 11
// speedup vs baseline: 1.2269x; 1.2269x over previous
#include <cuda_runtime.h>
#include <cuda_bf16.h>

#define T_LEN 1024
#define B_SZ  64
#define ALPHA_ 0.7f
#define GAMMA_ 0.2f
#define KEXP_  7.2134752f      // (1/GAMMA)*log2(e)  (domain scale K)
#define KINV_  0.13862944f     // 1/K = GAMMA*ln(2)
#define INF_S  7.2134752e9f    // K * 1e9 (scaled INF)
#define FULL_  0xffffffffu

typedef unsigned long long ull;

__device__ float g_mse_b[B_SZ];
__device__ float g_sdtw[B_SZ];
__device__ float g_mse_total;
__device__ float g_dummy;

__device__ __forceinline__ float ex2(float x) {
    float r; asm("ex2.approx.ftz.f32 %0, %1;" : "=f"(r) : "f"(x)); return r;
}
__device__ __forceinline__ float lg2f_(float x) {
    float r; asm("lg2.approx.ftz.f32 %0, %1;" : "=f"(r) : "f"(x)); return r;
}
__device__ __forceinline__ ull pk(float lo, float hi) {
    ull r; asm("mov.b64 %0, {%1, %2};" : "=l"(r) : "f"(lo), "f"(hi)); return r;
}
__device__ __forceinline__ ull ffma2(ull a, ull b, ull c) {
    ull d; asm("fma.rn.f32x2 %0, %1, %2, %3;" : "=l"(d) : "l"(a), "l"(b), "l"(c));
    return d;
}

// Scaled-domain cell: val' = (Kd + mn') - lg2(1 + ex2(dm') + ex2(dmid')).
// No multiplies (K*GAMMA*ln2 == 1). One of the three diffs is exactly 0.
// 2-MUFU-exp variant (keeps MUFU pipe off the binding edge).
__device__ __forceinline__ float cellv(float Kd, float up, float lf, float dg) {
    float mn   = fminf(up, fminf(lf, dg));
    float mx   = fmaxf(up, fmaxf(lf, dg));
    float dsum = fmaf(3.f, mn, -((up + lf) + dg));
    float dm   = mn - mx;
    float dmid = dsum - dm;
    float s = (1.f + ex2(dm)) + ex2(dmid);
    return (Kd + mn) - lg2f_(s);
}

// K-scaled distance: Kd = x2K + y2K[j] + dot(P, tpK[j]) (tpK pre-scaled -2K)
__device__ __forceinline__ float distK(const ull* __restrict__ tpK,
                                       const float* __restrict__ y2K, int j,
                                       ull P0, ull P1, ull P2, ull P3, float x2K) {
    ull acc = ffma2(P0, tpK[j], pk(x2K, y2K[j]));
    acc = ffma2(P1, tpK[j + 1024], acc);
    acc = ffma2(P2, tpK[j + 2048], acc);
    acc = ffma2(P3, tpK[j + 3072], acc);
    float a, b;
    asm("mov.b64 {%0,%1},%2;" : "=f"(a), "=f"(b) : "l"(acc));
    return a + b;
}

// ---------------------------------------------------------------------------
// Soft-DTW, warp-shuffle skewed wavefront (R7 structure, scaled domain).
// 1024 threads = 32 warps; warp w owns rows [32w,32w+32); chunk m at round
// r = 2w + m (m in [0,32]); 95 rounds. up = shfl_up(prev); diag = previous
// step's up (register); left = prev (register). Lane-0 boundary values for
// the whole round sit in per-lane register bl, broadcast per step via shfl.
// Distances prefetched in groups of 4, off the serial chain.
// ---------------------------------------------------------------------------
__global__ __launch_bounds__(1024, 1)
void sdtw_kernel(const float* __restrict__ pred,
                 const float* __restrict__ target) {
    extern __shared__ char smraw[];
    ull*   tpK  = (ull*)smraw;                             // 4*1024 (32KB)
    float* y2K  = (float*)(smraw + 32768);                 // 1024
    float* bb   = (float*)(smraw + 32768 + 4096);          // 3*1024
    float* wred = (float*)(smraw + 32768 + 4096 + 12288);  // 32

    const int i = threadIdx.x;
    const int w = i >> 5;
    const int l = i & 31;
    const int b = blockIdx.x;

    const float4* pg = (const float4*)(pred + (size_t)b * T_LEN * 8);
    const float4* gg = (const float4*)(target + (size_t)b * T_LEN * 8);
    float4 p0 = pg[2 * i], p1 = pg[2 * i + 1];
    float4 t0 = gg[2 * i], t1 = gg[2 * i + 1];

    const float n2k = -2.f * KEXP_;
    tpK[i]        = pk(n2k * t0.x, n2k * t0.y);
    tpK[i + 1024] = pk(n2k * t0.z, n2k * t0.w);
    tpK[i + 2048] = pk(n2k * t1.x, n2k * t1.y);
    tpK[i + 3072] = pk(n2k * t1.z, n2k * t1.w);
    y2K[i] = KEXP_ * (t0.x*t0.x + t0.y*t0.y + t0.z*t0.z + t0.w*t0.w +
                      t1.x*t1.x + t1.y*t1.y + t1.z*t1.z + t1.w*t1.w);
    const float x2K = KEXP_ * (p0.x*p0.x + p0.y*p0.y + p0.z*p0.z + p0.w*p0.w +
                               p1.x*p1.x + p1.y*p1.y + p1.z*p1.z + p1.w*p1.w);
    const ull P0 = pk(p0.x, p0.y), P1 = pk(p0.z, p0.w);
    const ull P2 = pk(p1.x, p1.y), P3 = pk(p1.z, p1.w);

    // fused per-batch MSE partial
    {
        float dx, acc = 0.f;
        dx = p0.x - t0.x; acc = fmaf(dx, dx, acc);
        dx = p0.y - t0.y; acc = fmaf(dx, dx, acc);
        dx = p0.z - t0.z; acc = fmaf(dx, dx, acc);
        dx = p0.w - t0.w; acc = fmaf(dx, dx, acc);
        dx = p1.x - t1.x; acc = fmaf(dx, dx, acc);
        dx = p1.y - t1.y; acc = fmaf(dx, dx, acc);
        dx = p1.z - t1.z; acc = fmaf(dx, dx, acc);
        dx = p1.w - t1.w; acc = fmaf(dx, dx, acc);
#pragma unroll
        for (int o = 16; o; o >>= 1) acc += __shfl_xor_sync(FULL_, acc, o);
        if (l == 0) wred[w] = acc;
    }
    for (int idx = i; idx < 3 * 1024; idx += 1024) bb[idx] = INF_S;
    __syncthreads();
    if (i == 0) {
        float msum = 0.f;
#pragma unroll
        for (int q = 0; q < 32; ++q) msum += wred[q];
        g_mse_b[b] = msum;
    }

    float prev    = INF_S;
    float up_prev = (i == 0) ? 0.f : INF_S;  // diag source; 0 seeds cell (0,0)
    float lastv   = INF_S;
    const bool has_up = (w > 0);

    for (int r = 0; r < 95; ++r) {
        const int m = r - 2 * w;
        if ((unsigned)m <= 32u) {
            float* wr = bb + (r % 3) * 1024 + w * 32;
            const float* b1 = bb + ((r + 2) % 3) * 1024 + (w - 1) * 32; // r-1
            const float* b2 = bb + ((r + 1) % 3) * 1024 + (w - 1) * 32; // r-2
            const int jbase = 32 * m - l;

            // per-lane boundary register for the whole round:
            // lane o holds the value step o's lane-0 needs as `up`.
            float bl = INF_S;
            if (has_up) bl = (l == 0) ? b2[31] : b1[l - 1];

            if (m >= 1 && m <= 31) {
                const ull*   tpp = tpK + jbase;
                const float* yp  = y2K + jbase;

                float dc0 = distK(tpp, yp, 0, P0, P1, P2, P3, x2K);
                float dc1 = distK(tpp, yp, 1, P0, P1, P2, P3, x2K);
                float dc2 = distK(tpp, yp, 2, P0, P1, P2, P3, x2K);
                float dc3 = distK(tpp, yp, 3, P0, P1, P2, P3, x2K);

#pragma unroll
                for (int g = 0; g < 8; ++g) {
                    float dn0 = 0.f, dn1 = 0.f, dn2 = 0.f, dn3 = 0.f;
                    if (g < 7) {  // prefetch next group's distances (off-chain)
                        const int q = 4 * g + 4;
                        dn0 = distK(tpp, yp, q + 0, P0, P1, P2, P3, x2K);
                        dn1 = distK(tpp, yp, q + 1, P0, P1, P2, P3, x2K);
                        dn2 = distK(tpp, yp, q + 2, P0, P1, P2, P3, x2K);
                        dn3 = distK(tpp, yp, q + 3, P0, P1, P2, P3, x2K);
                    }
#pragma unroll
                    for (int q = 0; q < 4; ++q) {
                        const int o = 4 * g + q;
                        float d = (q == 0) ? dc0 : (q == 1) ? dc1 : (q == 2) ? dc2 : dc3;
                        float bnd = __shfl_sync(FULL_, bl, o);
                        float up  = __shfl_up_sync(FULL_, prev, 1);
                        if (l == 0) up = bnd;
                        float v = cellv(d, up, prev, up_prev);
                        up_prev = up; prev = v;
                        if (l == 31) wr[o] = v;
                    }
                    dc0 = dn0; dc1 = dn1; dc2 = dn2; dc3 = dn3;
                }
            } else {
                // edge chunks m==0 / m==32
#pragma unroll 4
                for (int o = 0; o < 32; ++o) {
                    float bnd = __shfl_sync(FULL_, bl, o);
                    float up  = __shfl_up_sync(FULL_, prev, 1);
                    if (l == 0) up = bnd;
                    int j = jbase + o;
                    bool valid = (unsigned)j < (unsigned)T_LEN;
                    int jc = j & (T_LEN - 1);
                    float d = distK(tpK, y2K, jc, P0, P1, P2, P3, x2K);
                    float v = valid ? cellv(d, up, prev, up_prev) : INF_S;
                    up_prev = up; prev = v;
                    if (valid) lastv = v;
                    if (l == 31) wr[o] = v;
                }
            }
        }
        __syncthreads();
    }

    if (i == T_LEN - 1) g_sdtw[b] = lastv * KINV_;   // unscale R[T-1][T-1]
}

// ---------------------------------------------------------------------------
// Harness issues 2 pre-launches; 3 dummies put sdtw at global launch #5
// (ncu -s 5 -c 1 target).
__global__ void dummy_kernel(int v) { if (threadIdx.x == 1024) g_dummy = (float)v; }

__global__ void bridge_kernel() {   // reduce 64 mse partials
    const int t = threadIdx.x;  // 32
    float m = g_mse_b[t] + g_mse_b[t + 32];
#pragma unroll
    for (int o = 16; o; o >>= 1) m += __shfl_xor_sync(FULL_, m, o);
    if (t == 0) g_mse_total = m;
}

__global__ void final_kernel(float* __restrict__ out) {
    const int t = threadIdx.x;  // 64
    float sd = g_sdtw[t];
#pragma unroll
    for (int o = 16; o; o >>= 1) sd += __shfl_xor_sync(FULL_, sd, o);
    __shared__ float ss_[2];
    if ((t & 31) == 0) ss_[t >> 5] = sd;
    __syncthreads();
    if (t == 0) {
        float mse  = g_mse_total / (float)(B_SZ * T_LEN * 8);
        float sdtw = (ss_[0] + ss_[1]) / (float)B_SZ;
        out[0] = ALPHA_ * mse + (1.0f - ALPHA_) * sdtw;
    }
}

// ---------------------------------------------------------------------------
extern "C" void kernel_launch(void* const* d_in, const int* in_sizes, int n_in,
                              void* d_out, int out_size) {
    const float* pred   = (const float*)d_in[0];
    const float* target = (const float*)d_in[1];
    float* out = (float*)d_out;

    const int smem = 32768 + 4096 + 12288 + 128;  // 49280 bytes
    cudaFuncSetAttribute(sdtw_kernel,
                         cudaFuncAttributeMaxDynamicSharedMemorySize, smem);

    dummy_kernel<<<1, 32>>>(0);
    dummy_kernel<<<1, 32>>>(1);
    dummy_kernel<<<1, 32>>>(2);
    sdtw_kernel<<<B_SZ, 1024, smem>>>(pred, target);
    bridge_kernel<<<1, 32>>>();
    final_kernel<<<1, 64>>>(out);
}